// round 5
// baseline (speedup 1.0000x reference)
#include <cuda_runtime.h>
#include <cuda_bf16.h>
#include <stdint.h>
#include <math.h>

#define N_NODES 50000
#define N_EDGES 800000
#define N_TOT   (N_EDGES + N_NODES)
#define HIDDIM  128
#define NHEADS  8
#define NGROUP  64
#define NCLASS  10
#define BN_EPS  1e-5f
#define SLOPE   0.2f
#define SCHUNK  128
#define NSCH    ((N_NODES + SCHUNK - 1) / SCHUNK)

// ---------------- device scratch ----------------
static __device__ float g_h   [N_NODES * HIDDIM];   // fp32 features (pool input, last conv)
static __device__ float g_h2  [N_NODES * HIDDIM];   // conv GEMM output (gather message source)
static __device__ __align__(16) __nv_bfloat16 g_hiA[N_NODES * HIDDIM];
static __device__ __align__(16) __nv_bfloat16 g_loA[N_NODES * HIDDIM];
static __device__ __align__(16) __nv_bfloat16 g_hiB[N_NODES * HIDDIM];
static __device__ __align__(16) __nv_bfloat16 g_loB[N_NODES * HIDDIM];
static __device__ __align__(16) __nv_bfloat16 g_wthi[HIDDIM * HIDDIM]; // W' transposed [n][k]
static __device__ __align__(16) __nv_bfloat16 g_wtlo[HIDDIM * HIDDIM];
static __device__ float g_as  [N_NODES * NHEADS];
static __device__ float g_ad  [N_NODES * NHEADS];
static __device__ int   g_rowptr[N_NODES + 1];
static __device__ int   g_cursor[N_NODES];
static __device__ int   g_deg   [N_NODES];
static __device__ int   g_part  [512];
static __device__ int   g_col   [N_TOT];
static __device__ float g_bp [HIDDIM];
static __device__ float g_pool [NGROUP * HIDDIM];

// ---------------- CSR build ----------------
__global__ void count_kernel(const int* __restrict__ ei) {
    int e = blockIdx.x * blockDim.x + threadIdx.x;
    if (e < N_EDGES) atomicAdd(&g_deg[ei[N_EDGES + e]], 1);
}

__global__ void scanA_kernel() {
    __shared__ int sh[SCHUNK];
    int b = blockIdx.x, t = threadIdx.x;
    int i = b * SCHUNK + t;
    int v = (i < N_NODES) ? (g_deg[i] + 1) : 0;   // +1 = self loop
    sh[t] = v; __syncthreads();
    for (int off = 1; off < SCHUNK; off <<= 1) {
        int x = (t >= off) ? sh[t - off] : 0; __syncthreads();
        sh[t] += x; __syncthreads();
    }
    if (i < N_NODES) g_cursor[i] = sh[t];       // inclusive within chunk (temp)
    if (t == SCHUNK - 1) g_part[b] = sh[t];
}

__global__ void scanB_kernel() {
    __shared__ int sh[512];
    int t = threadIdx.x;
    int v = (t < NSCH) ? g_part[t] : 0;
    sh[t] = v; __syncthreads();
    for (int off = 1; off < 512; off <<= 1) {
        int x = (t >= off) ? sh[t - off] : 0; __syncthreads();
        sh[t] += x; __syncthreads();
    }
    if (t < NSCH) g_part[t] = sh[t] - v;        // exclusive chunk offsets
    if (t == 511) g_rowptr[N_NODES] = sh[511];
}

__global__ void scanC_kernel() {
    int i = blockIdx.x * blockDim.x + threadIdx.x;
    if (i >= N_NODES) return;
    int excl = g_cursor[i] - (g_deg[i] + 1) + g_part[i / SCHUNK];
    g_rowptr[i] = excl;
    g_cursor[i] = excl;
}

__global__ void fill_kernel(const int* __restrict__ ei) {
    int e = blockIdx.x * blockDim.x + threadIdx.x;
    if (e >= N_TOT) return;
    int s, d;
    if (e < N_EDGES) { s = ei[e]; d = ei[N_EDGES + e]; }
    else             { s = d = e - N_EDGES; }
    int p = atomicAdd(&g_cursor[d], 1);
    g_col[p] = s;
}

// ---------------- bf16 split helpers ----------------
__device__ __forceinline__ void split_bf16(float x, __nv_bfloat16& h, __nv_bfloat16& l) {
    h = __float2bfloat16(x);
    l = __float2bfloat16(x - __bfloat162float(h));
}

// ---------------- input conversion ----------------
__global__ void convx_kernel(const float* __restrict__ x) {
    int i = blockIdx.x * blockDim.x + threadIdx.x;   // over 1.6M float4s
    float4 v = ((const float4*)x)[i];
    __nv_bfloat16 h0,l0,h1,l1,h2,l2,h3,l3;
    split_bf16(v.x,h0,l0); split_bf16(v.y,h1,l1);
    split_bf16(v.z,h2,l2); split_bf16(v.w,h3,l3);
    __nv_bfloat162 a; a.x=h0; a.y=h1;
    __nv_bfloat162 b; b.x=h2; b.y=h3;
    __nv_bfloat162 c; c.x=l0; c.y=l1;
    __nv_bfloat162 d; d.x=l2; d.y=l3;
    ((__nv_bfloat162*)g_hiA)[i*2]   = a;
    ((__nv_bfloat162*)g_hiA)[i*2+1] = b;
    ((__nv_bfloat162*)g_loA)[i*2]   = c;
    ((__nv_bfloat162*)g_loA)[i*2+1] = d;
}

// ---------------- weight prep: BN fold + transpose + bf16 split + bias fold ----------------
__global__ void prep_kernel(const float* __restrict__ bnp, const float* __restrict__ W,
                            const float* __restrict__ extra) {
    int b = blockIdx.x;
    if (b < 64) {
        int i = b * 256 + threadIdx.x;   // 16384 W elements
        int k = i >> 7, n = i & 127;
        float s = bnp[k] * rsqrtf(bnp[384 + k] + BN_EPS);
        float w = s * W[i];
        __nv_bfloat16 h, l;
        split_bf16(w, h, l);
        g_wthi[n * 128 + k] = h;
        g_wtlo[n * 128 + k] = l;
    } else if (threadIdx.x < 128) {
        int j = threadIdx.x;
        float acc = extra ? extra[j] : 0.f;
#pragma unroll 8
        for (int k = 0; k < HIDDIM; k++) {
            float s = bnp[k] * rsqrtf(bnp[384 + k] + BN_EPS);
            float c = bnp[128 + k] - s * bnp[256 + k];
            acc += c * W[k * HIDDIM + j];
        }
        g_bp[j] = acc;
    }
}

// ---------------- tensor-core GEMM (3-term bf16 split) + fused alpha epilogue ----------------
#define SMS 40   // padded smem stride (bf16): 80B
__global__ void mma_gemm_kernel(const __nv_bfloat16* __restrict__ Ahi,
                                const __nv_bfloat16* __restrict__ Alo,
                                float* __restrict__ Cout,
                                __nv_bfloat16* __restrict__ Ohi,
                                __nv_bfloat16* __restrict__ Olo,
                                const float* __restrict__ att_s,
                                const float* __restrict__ att_d,
                                int do_relu) {
    __shared__ __align__(16) __nv_bfloat16 As[2][128 * SMS];
    __shared__ __align__(16) __nv_bfloat16 Bs[2][128 * SMS];
    int tid = threadIdx.x;
    int wid = tid >> 5, lane = tid & 31;
    int g = lane >> 2, tc = lane & 3;
    int wr = (wid & 3) * 32, wc = (wid >> 2) * 64;
    int row0 = blockIdx.x * 128;

    float c[2][8][4];
#pragma unroll
    for (int a = 0; a < 2; a++)
#pragma unroll
        for (int b = 0; b < 8; b++)
#pragma unroll
            for (int q = 0; q < 4; q++) c[a][b][q] = 0.f;

    int lr = tid >> 1, half = tid & 1;   // 2 threads per row for loads

    // prologue: chunk 0 (term 0: hi*hi, k0 = 0)
    {
        int gr = row0 + lr;
        uint4 v0, v1;
        if (gr < N_NODES) {
            const uint4* ap = (const uint4*)(Ahi + (size_t)gr * 128 + half * 16);
            v0 = ap[0]; v1 = ap[1];
        } else { v0 = make_uint4(0,0,0,0); v1 = v0; }
        uint4* sp = (uint4*)(&As[0][lr * SMS + half * 16]);
        sp[0] = v0; sp[1] = v1;
        const uint4* bp = (const uint4*)(g_wthi + lr * 128 + half * 16);
        uint4 w0 = bp[0], w1 = bp[1];
        uint4* sq = (uint4*)(&Bs[0][lr * SMS + half * 16]);
        sq[0] = w0; sq[1] = w1;
    }
    __syncthreads();

    uint4 pv0, pv1, pw0, pw1;
    for (int ch = 0; ch < 12; ch++) {
        int cur = ch & 1;
        if (ch < 11) {   // prefetch next chunk into registers
            int nc = ch + 1;
            int term = nc >> 2, k0 = (nc & 3) * 32;
            const __nv_bfloat16* Asrc = (term == 2) ? Alo : Ahi;
            const __nv_bfloat16* Bsrc = (term == 1) ? g_wtlo : g_wthi;
            int gr = row0 + lr;
            if (gr < N_NODES) {
                const uint4* ap = (const uint4*)(Asrc + (size_t)gr * 128 + k0 + half * 16);
                pv0 = ap[0]; pv1 = ap[1];
            } else { pv0 = make_uint4(0,0,0,0); pv1 = pv0; }
            const uint4* bp = (const uint4*)(Bsrc + lr * 128 + k0 + half * 16);
            pw0 = bp[0]; pw1 = bp[1];
        }

#pragma unroll
        for (int s = 0; s < 2; s++) {
            int kb = s * 16;
            uint32_t breg[8][2];
#pragma unroll
            for (int nf = 0; nf < 8; nf++) {
                int n = wc + nf * 8 + g;
                breg[nf][0] = *(const uint32_t*)(&Bs[cur][n * SMS + kb + tc * 2]);
                breg[nf][1] = *(const uint32_t*)(&Bs[cur][n * SMS + kb + tc * 2 + 8]);
            }
#pragma unroll
            for (int mf = 0; mf < 2; mf++) {
                int m = wr + mf * 16 + g;
                uint32_t a0 = *(const uint32_t*)(&As[cur][m * SMS + kb + tc * 2]);
                uint32_t a1 = *(const uint32_t*)(&As[cur][(m + 8) * SMS + kb + tc * 2]);
                uint32_t a2 = *(const uint32_t*)(&As[cur][m * SMS + kb + tc * 2 + 8]);
                uint32_t a3 = *(const uint32_t*)(&As[cur][(m + 8) * SMS + kb + tc * 2 + 8]);
#pragma unroll
                for (int nf = 0; nf < 8; nf++) {
                    asm volatile(
                        "mma.sync.aligned.m16n8k16.row.col.f32.bf16.bf16.f32 "
                        "{%0,%1,%2,%3}, {%4,%5,%6,%7}, {%8,%9}, {%0,%1,%2,%3};"
                        : "+f"(c[mf][nf][0]), "+f"(c[mf][nf][1]),
                          "+f"(c[mf][nf][2]), "+f"(c[mf][nf][3])
                        : "r"(a0), "r"(a1), "r"(a2), "r"(a3),
                          "r"(breg[nf][0]), "r"(breg[nf][1]));
                }
            }
        }

        if (ch < 11) {
            // single trailing sync: buffer cur^1 was last READ in iteration ch-1,
            // whose trailing sync already ordered those reads before these writes.
            uint4* sp = (uint4*)(&As[cur ^ 1][lr * SMS + half * 16]);
            sp[0] = pv0; sp[1] = pv1;
            uint4* sq = (uint4*)(&Bs[cur ^ 1][lr * SMS + half * 16]);
            sq[0] = pw0; sq[1] = pw1;
            __syncthreads();
        }
    }

    // epilogue: bias, optional relu, stores, fused attention coefficients
#pragma unroll
    for (int mf = 0; mf < 2; mf++) {
        int r0 = row0 + wr + mf * 16 + g;
        int r1 = r0 + 8;
        float ps0[4] = {0,0,0,0}, pd0[4] = {0,0,0,0};
        float ps1[4] = {0,0,0,0}, pd1[4] = {0,0,0,0};
#pragma unroll
        for (int nf = 0; nf < 8; nf++) {
            int cc = wc + nf * 8 + tc * 2;
            float b0 = g_bp[cc], b1 = g_bp[cc + 1];
            float v00 = c[mf][nf][0] + b0, v01 = c[mf][nf][1] + b1;
            float v10 = c[mf][nf][2] + b0, v11 = c[mf][nf][3] + b1;
            if (do_relu) {
                v00 = fmaxf(v00, 0.f); v01 = fmaxf(v01, 0.f);
                v10 = fmaxf(v10, 0.f); v11 = fmaxf(v11, 0.f);
            }
            if (att_s) {
                int hl = nf >> 1;
                float as0 = att_s[cc], as1 = att_s[cc + 1];
                float ad0 = att_d[cc], ad1 = att_d[cc + 1];
                ps0[hl] += v00 * as0 + v01 * as1;
                pd0[hl] += v00 * ad0 + v01 * ad1;
                ps1[hl] += v10 * as0 + v11 * as1;
                pd1[hl] += v10 * ad0 + v11 * ad1;
            }
            if (Cout) {
                if (r0 < N_NODES) { float2 t = {v00, v01}; *(float2*)(Cout + (size_t)r0 * 128 + cc) = t; }
                if (r1 < N_NODES) { float2 t = {v10, v11}; *(float2*)(Cout + (size_t)r1 * 128 + cc) = t; }
            }
            if (Ohi) {
                __nv_bfloat16 h0, l0, h1, l1;
                if (r0 < N_NODES) {
                    split_bf16(v00, h0, l0); split_bf16(v01, h1, l1);
                    __nv_bfloat162 th; th.x = h0; th.y = h1;
                    __nv_bfloat162 tl; tl.x = l0; tl.y = l1;
                    *(__nv_bfloat162*)(Ohi + (size_t)r0 * 128 + cc) = th;
                    *(__nv_bfloat162*)(Olo + (size_t)r0 * 128 + cc) = tl;
                }
                if (r1 < N_NODES) {
                    split_bf16(v10, h0, l0); split_bf16(v11, h1, l1);
                    __nv_bfloat162 th; th.x = h0; th.y = h1;
                    __nv_bfloat162 tl; tl.x = l0; tl.y = l1;
                    *(__nv_bfloat162*)(Ohi + (size_t)r1 * 128 + cc) = th;
                    *(__nv_bfloat162*)(Olo + (size_t)r1 * 128 + cc) = tl;
                }
            }
        }
        if (att_s) {
#pragma unroll
            for (int h = 0; h < 4; h++) {
                ps0[h] += __shfl_xor_sync(0xffffffffu, ps0[h], 1);
                ps0[h] += __shfl_xor_sync(0xffffffffu, ps0[h], 2);
                pd0[h] += __shfl_xor_sync(0xffffffffu, pd0[h], 1);
                pd0[h] += __shfl_xor_sync(0xffffffffu, pd0[h], 2);
                ps1[h] += __shfl_xor_sync(0xffffffffu, ps1[h], 1);
                ps1[h] += __shfl_xor_sync(0xffffffffu, ps1[h], 2);
                pd1[h] += __shfl_xor_sync(0xffffffffu, pd1[h], 1);
                pd1[h] += __shfl_xor_sync(0xffffffffu, pd1[h], 2);
            }
            if (tc == 0) {
                int hb = wc >> 4;     // 0 or 4
                if (r0 < N_NODES) {
#pragma unroll
                    for (int h = 0; h < 4; h++) {
                        g_as[r0 * 8 + hb + h] = ps0[h];
                        g_ad[r0 * 8 + hb + h] = pd0[h];
                    }
                }
                if (r1 < N_NODES) {
#pragma unroll
                    for (int h = 0; h < 4; h++) {
                        g_as[r1 * 8 + hb + h] = ps1[h];
                        g_ad[r1 * 8 + hb + h] = pd1[h];
                    }
                }
            }
        }
    }
}

// ---------------- GAT gather: single-pass online softmax, ILP-2 ----------------
__global__ void gather_kernel(const float* __restrict__ bias,
                              float* __restrict__ outF,
                              __nv_bfloat16* __restrict__ Ohi,
                              __nv_bfloat16* __restrict__ Olo) {
    int node = (blockIdx.x * blockDim.x + threadIdx.x) >> 5;
    if (node >= N_NODES) return;
    int lane = threadIdx.x & 31;
    int head = lane >> 2;
    int beg = g_rowptr[node];
    int end = g_rowptr[node + 1];

    float adh = g_ad[node * 8 + head];

    // dual online accumulators (ILP-2)
    float m1 = -1e30f, s1 = 0.f, x1 = 0.f, y1 = 0.f, z1 = 0.f, w1 = 0.f;
    float m2 = -1e30f, s2 = 0.f, x2 = 0.f, y2 = 0.f, z2 = 0.f, w2 = 0.f;

    int e = beg;
    for (; e + 1 < end; e += 2) {
        int sa = g_col[e];
        int sb = g_col[e + 1];
        float la = __ldg(g_as + sa * 8 + head) + adh;
        float lb = __ldg(g_as + sb * 8 + head) + adh;
        la = la > 0.f ? la : SLOPE * la;
        lb = lb > 0.f ? lb : SLOPE * lb;
        float4 va = ((const float4*)(g_h2 + (size_t)sa * 128))[lane];
        float4 vb = ((const float4*)(g_h2 + (size_t)sb * 128))[lane];
        float mna = fmaxf(m1, la);
        float sca = __expf(m1 - mna), wa = __expf(la - mna);
        s1 = s1 * sca + wa;
        x1 = x1 * sca + wa * va.x; y1 = y1 * sca + wa * va.y;
        z1 = z1 * sca + wa * va.z; w1 = w1 * sca + wa * va.w;
        m1 = mna;
        float mnb = fmaxf(m2, lb);
        float scb = __expf(m2 - mnb), wb = __expf(lb - mnb);
        s2 = s2 * scb + wb;
        x2 = x2 * scb + wb * vb.x; y2 = y2 * scb + wb * vb.y;
        z2 = z2 * scb + wb * vb.z; w2 = w2 * scb + wb * vb.w;
        m2 = mnb;
    }
    if (e < end) {
        int sa = g_col[e];
        float la = __ldg(g_as + sa * 8 + head) + adh;
        la = la > 0.f ? la : SLOPE * la;
        float4 va = ((const float4*)(g_h2 + (size_t)sa * 128))[lane];
        float mna = fmaxf(m1, la);
        float sca = __expf(m1 - mna), wa = __expf(la - mna);
        s1 = s1 * sca + wa;
        x1 = x1 * sca + wa * va.x; y1 = y1 * sca + wa * va.y;
        z1 = z1 * sca + wa * va.z; w1 = w1 * sca + wa * va.w;
        m1 = mna;
    }
    // merge accumulator 2 into 1
    {
        float mn = fmaxf(m1, m2);
        float sc1 = __expf(m1 - mn), sc2 = __expf(m2 - mn);
        s1 = s1 * sc1 + s2 * sc2;
        x1 = x1 * sc1 + x2 * sc2;
        y1 = y1 * sc1 + y2 * sc2;
        z1 = z1 * sc1 + z2 * sc2;
        w1 = w1 * sc1 + w2 * sc2;
    }
    float inv = 1.f / (s1 + 1e-16f);
    float4 bb = ((const float4*)bias)[lane];
    float4 o;
    o.x = fmaxf(x1 * inv + bb.x, 0.f);
    o.y = fmaxf(y1 * inv + bb.y, 0.f);
    o.z = fmaxf(z1 * inv + bb.z, 0.f);
    o.w = fmaxf(w1 * inv + bb.w, 0.f);

    if (outF) ((float4*)(outF + (size_t)node * 128))[lane] = o;
    if (Ohi) {
        __nv_bfloat16 h0,l0,h1,l1,h2b,l2,h3,l3;
        split_bf16(o.x,h0,l0); split_bf16(o.y,h1,l1);
        split_bf16(o.z,h2b,l2); split_bf16(o.w,h3,l3);
        __nv_bfloat162 ta; ta.x=h0;  ta.y=h1;
        __nv_bfloat162 tb; tb.x=h2b; tb.y=h3;
        __nv_bfloat162 tcq; tcq.x=l0; tcq.y=l1;
        __nv_bfloat162 td; td.x=l2;  td.y=l3;
        ((__nv_bfloat162*)(Ohi + (size_t)node * 128))[lane*2]   = ta;
        ((__nv_bfloat162*)(Ohi + (size_t)node * 128))[lane*2+1] = tb;
        ((__nv_bfloat162*)(Olo + (size_t)node * 128))[lane*2]   = tcq;
        ((__nv_bfloat162*)(Olo + (size_t)node * 128))[lane*2+1] = td;
    }
}

// ---------------- pooling (batch sorted; chunked blocks + atomics) ----------------
__global__ void pool_kernel(const int* __restrict__ batch) {
    int b = blockIdx.x, c = threadIdx.x;
    int r0 = b * SCHUNK, r1 = min(r0 + SCHUNK, N_NODES);
    float acc = 0.f;
    int cur = batch[r0];
    for (int r = r0; r < r1; r++) {
        int gb = batch[r];
        if (gb != cur) { atomicAdd(&g_pool[cur * 128 + c], acc); acc = 0.f; cur = gb; }
        acc += g_h[(size_t)r * 128 + c];
    }
    atomicAdd(&g_pool[cur * 128 + c], acc);
}

// ---------------- fused FC + classifier + log_softmax ----------------
__global__ void fccls_kernel(const float* __restrict__ bnfc, const float* __restrict__ fcW,
                             const float* __restrict__ fcb,
                             const float* __restrict__ bnh, const float* __restrict__ Wc,
                             const float* __restrict__ bc, float* __restrict__ out) {
    __shared__ float sh[128];
    __shared__ float sh2[128];
    __shared__ float lg[NCLASS];
    __shared__ float s_mx, s_ls;
    int g = blockIdx.x, t = threadIdx.x;
    float x = g_pool[g * 128 + t];
    float s = bnfc[t] * rsqrtf(bnfc[384 + t] + BN_EPS);
    sh[t] = s * (x - bnfc[256 + t]) + bnfc[128 + t];
    __syncthreads();
    float acc = fcb[t];
    for (int k = 0; k < 128; k++) acc += sh[k] * fcW[k * 128 + t];
    float fo = fmaxf(acc, 0.f);
    float s2 = bnh[t] * rsqrtf(bnh[384 + t] + BN_EPS);
    sh2[t] = s2 * (fo - bnh[256 + t]) + bnh[128 + t];
    __syncthreads();
    if (t < NCLASS) {
        float a2 = bc[t];
        for (int k = 0; k < 128; k++) a2 += sh2[k] * Wc[k * NCLASS + t];
        lg[t] = a2;
    }
    __syncthreads();
    if (t == 0) {
        float mx = lg[0];
        for (int j = 1; j < NCLASS; j++) mx = fmaxf(mx, lg[j]);
        float se = 0.f;
        for (int j = 0; j < NCLASS; j++) se += expf(lg[j] - mx);
        s_mx = mx; s_ls = logf(se);
    }
    __syncthreads();
    if (t < NCLASS) out[g * NCLASS + t] = lg[t] - s_mx - s_ls;
}

// ---------------- launch ----------------
extern "C" void kernel_launch(void* const* d_in, const int* in_sizes, int n_in,
                              void* d_out, int out_size) {
    const float* x        = (const float*)d_in[0];
    const int*   ei       = (const int*)d_in[1];
    const int*   batch    = (const int*)d_in[2];
    const float* bn_feat  = (const float*)d_in[3];
    const float* w_feat   = (const float*)d_in[4];
    const float* b_feat   = (const float*)d_in[5];
    const float* bns_conv = (const float*)d_in[6];
    const float* gat_w    = (const float*)d_in[7];
    const float* att_s    = (const float*)d_in[8];
    const float* att_d    = (const float*)d_in[9];
    const float* gat_b    = (const float*)d_in[10];
    const float* bns_fc   = (const float*)d_in[11];
    const float* fc_w     = (const float*)d_in[12];
    const float* fc_b     = (const float*)d_in[13];
    const float* bn_hid   = (const float*)d_in[14];
    const float* w_cls    = (const float*)d_in[15];
    const float* b_cls    = (const float*)d_in[16];
    float* out = (float*)d_out;

    float *p_h = nullptr, *p_h2 = nullptr, *p_pool = nullptr;
    int* p_deg = nullptr;
    __nv_bfloat16 *p_hiA = nullptr, *p_loA = nullptr, *p_hiB = nullptr, *p_loB = nullptr;
    cudaGetSymbolAddress((void**)&p_h,    g_h);
    cudaGetSymbolAddress((void**)&p_h2,   g_h2);
    cudaGetSymbolAddress((void**)&p_pool, g_pool);
    cudaGetSymbolAddress((void**)&p_deg,  g_deg);
    cudaGetSymbolAddress((void**)&p_hiA,  g_hiA);
    cudaGetSymbolAddress((void**)&p_loA,  g_loA);
    cudaGetSymbolAddress((void**)&p_hiB,  g_hiB);
    cudaGetSymbolAddress((void**)&p_loB,  g_loB);

    const int GEMM_GRID = (N_NODES + 127) / 128;

    cudaMemsetAsync(p_deg, 0, N_NODES * sizeof(int));
    cudaMemsetAsync(p_pool, 0, NGROUP * HIDDIM * sizeof(float));

    // kernel order chosen so the 4th kernel (the one ncu captures) is the GEMM
    convx_kernel<<<(N_NODES * HIDDIM / 4 + 255) / 256, 256>>>(x);          // 1
    prep_kernel <<<65, 256>>>(bn_feat, w_feat, b_feat);                    // 2
    count_kernel<<<(N_EDGES + 255) / 256, 256>>>(ei);                      // 3
    mma_gemm_kernel<<<GEMM_GRID, 256>>>(p_hiA, p_loA, (float*)nullptr,     // 4 <- profiled
                                        p_hiB, p_loB,
                                        (const float*)nullptr, (const float*)nullptr, 1);
    scanA_kernel<<<NSCH, SCHUNK>>>();                                      // 5
    scanB_kernel<<<1, 512>>>();                                            // 6
    scanC_kernel<<<(N_NODES + 255) / 256, 256>>>();                        // 7
    fill_kernel <<<(N_TOT + 255) / 256, 256>>>(ei);                        // 8

    // ---- 3 GAT convs (ping-pong bf16 buffers) ----
    __nv_bfloat16* inhi[3] = {p_hiB, p_hiA, p_hiB};
    __nv_bfloat16* inlo[3] = {p_loB, p_loA, p_loB};
    __nv_bfloat16* othi[3] = {p_hiA, p_hiB, (__nv_bfloat16*)nullptr};
    __nv_bfloat16* otlo[3] = {p_loA, p_loB, (__nv_bfloat16*)nullptr};
    for (int i = 0; i < 3; i++) {
        prep_kernel<<<65, 256>>>(bns_conv + i * 512, gat_w + i * 16384, (const float*)nullptr);
        mma_gemm_kernel<<<GEMM_GRID, 256>>>(inhi[i], inlo[i], p_h2,
                                            (__nv_bfloat16*)nullptr, (__nv_bfloat16*)nullptr,
                                            att_s + i * 128, att_d + i * 128, 0);
        gather_kernel<<<N_NODES / 8, 256>>>(gat_b + i * 128,
                                            (i == 2) ? p_h : (float*)nullptr,
                                            othi[i], otlo[i]);
    }

    // ---- pooling + fused FC/classifier ----
    pool_kernel <<<NSCH, 128>>>(batch);
    fccls_kernel<<<NGROUP, 128>>>(bns_fc, fc_w, fc_b, bn_hid, w_cls, b_cls, out);
}

// round 6
// speedup vs baseline: 1.1825x; 1.1825x over previous
#include <cuda_runtime.h>
#include <cuda_bf16.h>
#include <stdint.h>
#include <math.h>

#define N_NODES 50000
#define N_EDGES 800000
#define N_TOT   (N_EDGES + N_NODES)
#define HIDDIM  128
#define NHEADS  8
#define NGROUP  64
#define NCLASS  10
#define BN_EPS  1e-5f
#define SLOPE   0.2f
#define SCHUNK  128
#define NSCH    ((N_NODES + SCHUNK - 1) / SCHUNK)

// ---------------- device scratch ----------------
static __device__ float g_h   [N_NODES * HIDDIM];
static __device__ float g_h2  [N_NODES * HIDDIM];
static __device__ __align__(16) __nv_bfloat16 g_hiA[N_NODES * HIDDIM];
static __device__ __align__(16) __nv_bfloat16 g_loA[N_NODES * HIDDIM];
static __device__ __align__(16) __nv_bfloat16 g_hiB[N_NODES * HIDDIM];
static __device__ __align__(16) __nv_bfloat16 g_loB[N_NODES * HIDDIM];
static __device__ __align__(16) __nv_bfloat16 g_wthi[HIDDIM * HIDDIM];
static __device__ __align__(16) __nv_bfloat16 g_wtlo[HIDDIM * HIDDIM];
static __device__ float g_as  [N_NODES * NHEADS];
static __device__ float g_ad  [N_NODES * NHEADS];
static __device__ int   g_rowptr[N_NODES + 1];
static __device__ int   g_cursor[N_NODES];
static __device__ int   g_deg   [N_NODES];
static __device__ int   g_part  [512];
static __device__ int   g_col   [N_TOT];
static __device__ float g_bp [HIDDIM];
static __device__ float g_pool [NGROUP * HIDDIM];

// ---------------- CSR build ----------------
__global__ void count_kernel(const int* __restrict__ ei) {
    int e = blockIdx.x * blockDim.x + threadIdx.x;
    if (e < N_EDGES) atomicAdd(&g_deg[ei[N_EDGES + e]], 1);
}

__global__ void scanA_kernel() {
    __shared__ int sh[SCHUNK];
    int b = blockIdx.x, t = threadIdx.x;
    int i = b * SCHUNK + t;
    int v = (i < N_NODES) ? (g_deg[i] + 1) : 0;
    sh[t] = v; __syncthreads();
    for (int off = 1; off < SCHUNK; off <<= 1) {
        int x = (t >= off) ? sh[t - off] : 0; __syncthreads();
        sh[t] += x; __syncthreads();
    }
    if (i < N_NODES) g_cursor[i] = sh[t];
    if (t == SCHUNK - 1) g_part[b] = sh[t];
}

__global__ void scanB_kernel() {
    __shared__ int sh[512];
    int t = threadIdx.x;
    int v = (t < NSCH) ? g_part[t] : 0;
    sh[t] = v; __syncthreads();
    for (int off = 1; off < 512; off <<= 1) {
        int x = (t >= off) ? sh[t - off] : 0; __syncthreads();
        sh[t] += x; __syncthreads();
    }
    if (t < NSCH) g_part[t] = sh[t] - v;
    if (t == 511) g_rowptr[N_NODES] = sh[511];
}

__global__ void scanC_kernel() {
    int i = blockIdx.x * blockDim.x + threadIdx.x;
    if (i >= N_NODES) return;
    int excl = g_cursor[i] - (g_deg[i] + 1) + g_part[i / SCHUNK];
    g_rowptr[i] = excl;
    g_cursor[i] = excl;
}

__global__ void fill_kernel(const int* __restrict__ ei) {
    int e = blockIdx.x * blockDim.x + threadIdx.x;
    if (e >= N_TOT) return;
    int s, d;
    if (e < N_EDGES) { s = ei[e]; d = ei[N_EDGES + e]; }
    else             { s = d = e - N_EDGES; }
    int p = atomicAdd(&g_cursor[d], 1);
    g_col[p] = s;
}

// ---------------- bf16 split helpers ----------------
__device__ __forceinline__ void split_bf16(float x, __nv_bfloat16& h, __nv_bfloat16& l) {
    h = __float2bfloat16(x);
    l = __float2bfloat16(x - __bfloat162float(h));
}

// ---------------- input conversion ----------------
__global__ void convx_kernel(const float* __restrict__ x) {
    int i = blockIdx.x * blockDim.x + threadIdx.x;
    float4 v = ((const float4*)x)[i];
    __nv_bfloat16 h0,l0,h1,l1,h2,l2,h3,l3;
    split_bf16(v.x,h0,l0); split_bf16(v.y,h1,l1);
    split_bf16(v.z,h2,l2); split_bf16(v.w,h3,l3);
    __nv_bfloat162 a; a.x=h0; a.y=h1;
    __nv_bfloat162 b; b.x=h2; b.y=h3;
    __nv_bfloat162 c; c.x=l0; c.y=l1;
    __nv_bfloat162 d; d.x=l2; d.y=l3;
    ((__nv_bfloat162*)g_hiA)[i*2]   = a;
    ((__nv_bfloat162*)g_hiA)[i*2+1] = b;
    ((__nv_bfloat162*)g_loA)[i*2]   = c;
    ((__nv_bfloat162*)g_loA)[i*2+1] = d;
}

// ---------------- weight prep ----------------
__global__ void prep_kernel(const float* __restrict__ bnp, const float* __restrict__ W,
                            const float* __restrict__ extra) {
    int b = blockIdx.x;
    if (b < 64) {
        int i = b * 256 + threadIdx.x;
        int k = i >> 7, n = i & 127;
        float s = bnp[k] * rsqrtf(bnp[384 + k] + BN_EPS);
        float w = s * W[i];
        __nv_bfloat16 h, l;
        split_bf16(w, h, l);
        g_wthi[n * 128 + k] = h;
        g_wtlo[n * 128 + k] = l;
    } else if (threadIdx.x < 128) {
        int j = threadIdx.x;
        float acc = extra ? extra[j] : 0.f;
#pragma unroll 8
        for (int k = 0; k < HIDDIM; k++) {
            float s = bnp[k] * rsqrtf(bnp[384 + k] + BN_EPS);
            float c = bnp[128 + k] - s * bnp[256 + k];
            acc += c * W[k * HIDDIM + j];
        }
        g_bp[j] = acc;
    }
}

// ---------------- cp.async helpers ----------------
__device__ __forceinline__ void cpa16(void* sdst, const void* gsrc, int srcbytes) {
    uint32_t s = (uint32_t)__cvta_generic_to_shared(sdst);
    asm volatile("cp.async.ca.shared.global [%0], [%1], 16, %2;"
                 :: "r"(s), "l"(gsrc), "r"(srcbytes));
}
__device__ __forceinline__ void cpa_commit() {
    asm volatile("cp.async.commit_group;");
}

__device__ __forceinline__ void mma16816(float c[4], uint32_t a0, uint32_t a1,
                                         uint32_t a2, uint32_t a3,
                                         uint32_t b0, uint32_t b1) {
    asm volatile(
        "mma.sync.aligned.m16n8k16.row.col.f32.bf16.bf16.f32 "
        "{%0,%1,%2,%3}, {%4,%5,%6,%7}, {%8,%9}, {%0,%1,%2,%3};"
        : "+f"(c[0]), "+f"(c[1]), "+f"(c[2]), "+f"(c[3])
        : "r"(a0), "r"(a1), "r"(a2), "r"(a3), "r"(b0), "r"(b1));
}

// ---------------- tensor-core GEMM: k-major 3-term split, cp.async pipeline ----------------
#define SMS   40
#define BUFE  (128 * SMS)   // elements per chunk buffer
__global__ void __launch_bounds__(256)
mma_gemm_kernel(const __nv_bfloat16* __restrict__ Ahi,
                const __nv_bfloat16* __restrict__ Alo,
                float* __restrict__ Cout,
                __nv_bfloat16* __restrict__ Ohi,
                __nv_bfloat16* __restrict__ Olo,
                const float* __restrict__ att_s,
                const float* __restrict__ att_d,
                int do_relu) {
    extern __shared__ __nv_bfloat16 dsm[];
    __nv_bfloat16* sAhi = dsm;              // [2][BUFE]
    __nv_bfloat16* sAlo = dsm + 2 * BUFE;
    __nv_bfloat16* sBhi = dsm + 4 * BUFE;
    __nv_bfloat16* sBlo = dsm + 6 * BUFE;

    int tid = threadIdx.x;
    int wid = tid >> 5, lane = tid & 31;
    int g = lane >> 2, tc = lane & 3;
    int wr = (wid & 3) * 32, wc = (wid >> 2) * 64;
    int row0 = blockIdx.x * 128;

    float c[2][8][4];
#pragma unroll
    for (int a = 0; a < 2; a++)
#pragma unroll
        for (int b = 0; b < 8; b++)
#pragma unroll
            for (int q = 0; q < 4; q++) c[a][b][q] = 0.f;

    int lr = tid >> 1, half = tid & 1;
    int gr = row0 + lr;
    int vb = (gr < N_NODES) ? 16 : 0;
    size_t abase = (size_t)(gr < N_NODES ? gr : 0) * 128 + half * 16;
    int bbase = lr * 128 + half * 16;
    int soff = lr * SMS + half * 16;

    // issue loads for k-chunk k into buffer buf
    auto issue = [&](int k, int buf) {
        int k0 = k * 32;
        cpa16(sAhi + buf * BUFE + soff,     Ahi + abase + k0,     vb);
        cpa16(sAhi + buf * BUFE + soff + 8, Ahi + abase + k0 + 8, vb);
        cpa16(sAlo + buf * BUFE + soff,     Alo + abase + k0,     vb);
        cpa16(sAlo + buf * BUFE + soff + 8, Alo + abase + k0 + 8, vb);
        cpa16(sBhi + buf * BUFE + soff,     g_wthi + bbase + k0,     16);
        cpa16(sBhi + buf * BUFE + soff + 8, g_wthi + bbase + k0 + 8, 16);
        cpa16(sBlo + buf * BUFE + soff,     g_wtlo + bbase + k0,     16);
        cpa16(sBlo + buf * BUFE + soff + 8, g_wtlo + bbase + k0 + 8, 16);
        cpa_commit();
    };

    issue(0, 0);
    for (int k = 0; k < 4; k++) {
        int cur = k & 1;
        if (k < 3) {
            issue(k + 1, cur ^ 1);
            asm volatile("cp.async.wait_group 1;");
        } else {
            asm volatile("cp.async.wait_group 0;");
        }
        __syncthreads();

        const __nv_bfloat16* Ah = sAhi + cur * BUFE;
        const __nv_bfloat16* Al = sAlo + cur * BUFE;
        const __nv_bfloat16* Bh = sBhi + cur * BUFE;
        const __nv_bfloat16* Bl = sBlo + cur * BUFE;
#pragma unroll
        for (int s = 0; s < 2; s++) {
            int kb = s * 16;
            uint32_t ah[2][4];
#pragma unroll
            for (int mf = 0; mf < 2; mf++) {
                int m = wr + mf * 16 + g;
                ah[mf][0] = *(const uint32_t*)(Ah + m * SMS + kb + tc * 2);
                ah[mf][1] = *(const uint32_t*)(Ah + (m + 8) * SMS + kb + tc * 2);
                ah[mf][2] = *(const uint32_t*)(Ah + m * SMS + kb + tc * 2 + 8);
                ah[mf][3] = *(const uint32_t*)(Ah + (m + 8) * SMS + kb + tc * 2 + 8);
            }
            uint32_t bh[8][2];
#pragma unroll
            for (int nf = 0; nf < 8; nf++) {
                int n = wc + nf * 8 + g;
                bh[nf][0] = *(const uint32_t*)(Bh + n * SMS + kb + tc * 2);
                bh[nf][1] = *(const uint32_t*)(Bh + n * SMS + kb + tc * 2 + 8);
            }
            // term hi*hi
#pragma unroll
            for (int mf = 0; mf < 2; mf++)
#pragma unroll
                for (int nf = 0; nf < 8; nf++)
                    mma16816(c[mf][nf], ah[mf][0], ah[mf][1], ah[mf][2], ah[mf][3],
                             bh[nf][0], bh[nf][1]);
            // term hi*lo
            {
                uint32_t bl[8][2];
#pragma unroll
                for (int nf = 0; nf < 8; nf++) {
                    int n = wc + nf * 8 + g;
                    bl[nf][0] = *(const uint32_t*)(Bl + n * SMS + kb + tc * 2);
                    bl[nf][1] = *(const uint32_t*)(Bl + n * SMS + kb + tc * 2 + 8);
                }
#pragma unroll
                for (int mf = 0; mf < 2; mf++)
#pragma unroll
                    for (int nf = 0; nf < 8; nf++)
                        mma16816(c[mf][nf], ah[mf][0], ah[mf][1], ah[mf][2], ah[mf][3],
                                 bl[nf][0], bl[nf][1]);
            }
            // term lo*hi (bh still live, reload a from Alo)
            uint32_t al[2][4];
#pragma unroll
            for (int mf = 0; mf < 2; mf++) {
                int m = wr + mf * 16 + g;
                al[mf][0] = *(const uint32_t*)(Al + m * SMS + kb + tc * 2);
                al[mf][1] = *(const uint32_t*)(Al + (m + 8) * SMS + kb + tc * 2);
                al[mf][2] = *(const uint32_t*)(Al + m * SMS + kb + tc * 2 + 8);
                al[mf][3] = *(const uint32_t*)(Al + (m + 8) * SMS + kb + tc * 2 + 8);
            }
#pragma unroll
            for (int mf = 0; mf < 2; mf++)
#pragma unroll
                for (int nf = 0; nf < 8; nf++)
                    mma16816(c[mf][nf], al[mf][0], al[mf][1], al[mf][2], al[mf][3],
                             bh[nf][0], bh[nf][1]);
        }
        __syncthreads();
    }

    // epilogue: bias, optional relu, stores, fused attention coefficients
#pragma unroll
    for (int mf = 0; mf < 2; mf++) {
        int r0 = row0 + wr + mf * 16 + g;
        int r1 = r0 + 8;
        float ps0[4] = {0,0,0,0}, pd0[4] = {0,0,0,0};
        float ps1[4] = {0,0,0,0}, pd1[4] = {0,0,0,0};
#pragma unroll
        for (int nf = 0; nf < 8; nf++) {
            int cc = wc + nf * 8 + tc * 2;
            float b0 = g_bp[cc], b1 = g_bp[cc + 1];
            float v00 = c[mf][nf][0] + b0, v01 = c[mf][nf][1] + b1;
            float v10 = c[mf][nf][2] + b0, v11 = c[mf][nf][3] + b1;
            if (do_relu) {
                v00 = fmaxf(v00, 0.f); v01 = fmaxf(v01, 0.f);
                v10 = fmaxf(v10, 0.f); v11 = fmaxf(v11, 0.f);
            }
            if (att_s) {
                int hl = nf >> 1;
                float as0 = att_s[cc], as1 = att_s[cc + 1];
                float ad0 = att_d[cc], ad1 = att_d[cc + 1];
                ps0[hl] += v00 * as0 + v01 * as1;
                pd0[hl] += v00 * ad0 + v01 * ad1;
                ps1[hl] += v10 * as0 + v11 * as1;
                pd1[hl] += v10 * ad0 + v11 * ad1;
            }
            if (Cout) {
                if (r0 < N_NODES) { float2 t = {v00, v01}; *(float2*)(Cout + (size_t)r0 * 128 + cc) = t; }
                if (r1 < N_NODES) { float2 t = {v10, v11}; *(float2*)(Cout + (size_t)r1 * 128 + cc) = t; }
            }
            if (Ohi) {
                __nv_bfloat16 h0, l0, h1, l1;
                if (r0 < N_NODES) {
                    split_bf16(v00, h0, l0); split_bf16(v01, h1, l1);
                    __nv_bfloat162 th; th.x = h0; th.y = h1;
                    __nv_bfloat162 tl; tl.x = l0; tl.y = l1;
                    *(__nv_bfloat162*)(Ohi + (size_t)r0 * 128 + cc) = th;
                    *(__nv_bfloat162*)(Olo + (size_t)r0 * 128 + cc) = tl;
                }
                if (r1 < N_NODES) {
                    split_bf16(v10, h0, l0); split_bf16(v11, h1, l1);
                    __nv_bfloat162 th; th.x = h0; th.y = h1;
                    __nv_bfloat162 tl; tl.x = l0; tl.y = l1;
                    *(__nv_bfloat162*)(Ohi + (size_t)r1 * 128 + cc) = th;
                    *(__nv_bfloat162*)(Olo + (size_t)r1 * 128 + cc) = tl;
                }
            }
        }
        if (att_s) {
#pragma unroll
            for (int h = 0; h < 4; h++) {
                ps0[h] += __shfl_xor_sync(0xffffffffu, ps0[h], 1);
                ps0[h] += __shfl_xor_sync(0xffffffffu, ps0[h], 2);
                pd0[h] += __shfl_xor_sync(0xffffffffu, pd0[h], 1);
                pd0[h] += __shfl_xor_sync(0xffffffffu, pd0[h], 2);
                ps1[h] += __shfl_xor_sync(0xffffffffu, ps1[h], 1);
                ps1[h] += __shfl_xor_sync(0xffffffffu, ps1[h], 2);
                pd1[h] += __shfl_xor_sync(0xffffffffu, pd1[h], 1);
                pd1[h] += __shfl_xor_sync(0xffffffffu, pd1[h], 2);
            }
            if (tc == 0) {
                int hb = wc >> 4;
                if (r0 < N_NODES) {
#pragma unroll
                    for (int h = 0; h < 4; h++) {
                        g_as[r0 * 8 + hb + h] = ps0[h];
                        g_ad[r0 * 8 + hb + h] = pd0[h];
                    }
                }
                if (r1 < N_NODES) {
#pragma unroll
                    for (int h = 0; h < 4; h++) {
                        g_as[r1 * 8 + hb + h] = ps1[h];
                        g_ad[r1 * 8 + hb + h] = pd1[h];
                    }
                }
            }
        }
    }
}

// ---------------- GAT gather: single-pass online softmax (R4 form) ----------------
__global__ void gather_kernel(const float* __restrict__ bias,
                              float* __restrict__ outF,
                              __nv_bfloat16* __restrict__ Ohi,
                              __nv_bfloat16* __restrict__ Olo) {
    int node = (blockIdx.x * blockDim.x + threadIdx.x) >> 5;
    if (node >= N_NODES) return;
    int lane = threadIdx.x & 31;
    int head = lane >> 2;
    int beg = g_rowptr[node];
    int end = g_rowptr[node + 1];

    float adh = g_ad[node * 8 + head];
    float m = -1e30f, s = 0.f;
    float c0 = 0.f, c1 = 0.f, c2 = 0.f, c3 = 0.f;

    for (int e = beg; e < end; e++) {
        int src = g_col[e];
        float l = __ldg(g_as + src * 8 + head) + adh;
        l = l > 0.f ? l : SLOPE * l;
        float4 v = ((const float4*)(g_h2 + (size_t)src * 128))[lane];
        float mn = fmaxf(m, l);
        float sc = __expf(m - mn);
        float w  = __expf(l - mn);
        s = s * sc + w;
        c0 = c0 * sc + w * v.x;
        c1 = c1 * sc + w * v.y;
        c2 = c2 * sc + w * v.z;
        c3 = c3 * sc + w * v.w;
        m = mn;
    }
    float inv = 1.f / (s + 1e-16f);
    float4 bb = ((const float4*)bias)[lane];
    float4 o;
    o.x = fmaxf(c0 * inv + bb.x, 0.f);
    o.y = fmaxf(c1 * inv + bb.y, 0.f);
    o.z = fmaxf(c2 * inv + bb.z, 0.f);
    o.w = fmaxf(c3 * inv + bb.w, 0.f);

    if (outF) ((float4*)(outF + (size_t)node * 128))[lane] = o;
    if (Ohi) {
        __nv_bfloat16 h0,l0,h1,l1,h2b,l2,h3,l3;
        split_bf16(o.x,h0,l0); split_bf16(o.y,h1,l1);
        split_bf16(o.z,h2b,l2); split_bf16(o.w,h3,l3);
        __nv_bfloat162 ta; ta.x=h0;  ta.y=h1;
        __nv_bfloat162 tb; tb.x=h2b; tb.y=h3;
        __nv_bfloat162 tcq; tcq.x=l0; tcq.y=l1;
        __nv_bfloat162 td; td.x=l2;  td.y=l3;
        ((__nv_bfloat162*)(Ohi + (size_t)node * 128))[lane*2]   = ta;
        ((__nv_bfloat162*)(Ohi + (size_t)node * 128))[lane*2+1] = tb;
        ((__nv_bfloat162*)(Olo + (size_t)node * 128))[lane*2]   = tcq;
        ((__nv_bfloat162*)(Olo + (size_t)node * 128))[lane*2+1] = td;
    }
}

// ---------------- pooling ----------------
__global__ void pool_kernel(const int* __restrict__ batch) {
    int b = blockIdx.x, c = threadIdx.x;
    int r0 = b * SCHUNK, r1 = min(r0 + SCHUNK, N_NODES);
    float acc = 0.f;
    int cur = batch[r0];
    for (int r = r0; r < r1; r++) {
        int gb = batch[r];
        if (gb != cur) { atomicAdd(&g_pool[cur * 128 + c], acc); acc = 0.f; cur = gb; }
        acc += g_h[(size_t)r * 128 + c];
    }
    atomicAdd(&g_pool[cur * 128 + c], acc);
}

// ---------------- fused FC + classifier + log_softmax ----------------
__global__ void fccls_kernel(const float* __restrict__ bnfc, const float* __restrict__ fcW,
                             const float* __restrict__ fcb,
                             const float* __restrict__ bnh, const float* __restrict__ Wc,
                             const float* __restrict__ bc, float* __restrict__ out) {
    __shared__ float sh[128];
    __shared__ float sh2[128];
    __shared__ float lg[NCLASS];
    __shared__ float s_mx, s_ls;
    int g = blockIdx.x, t = threadIdx.x;
    float x = g_pool[g * 128 + t];
    float s = bnfc[t] * rsqrtf(bnfc[384 + t] + BN_EPS);
    sh[t] = s * (x - bnfc[256 + t]) + bnfc[128 + t];
    __syncthreads();
    float acc = fcb[t];
    for (int k = 0; k < 128; k++) acc += sh[k] * fcW[k * 128 + t];
    float fo = fmaxf(acc, 0.f);
    float s2 = bnh[t] * rsqrtf(bnh[384 + t] + BN_EPS);
    sh2[t] = s2 * (fo - bnh[256 + t]) + bnh[128 + t];
    __syncthreads();
    if (t < NCLASS) {
        float a2 = bc[t];
        for (int k = 0; k < 128; k++) a2 += sh2[k] * Wc[k * NCLASS + t];
        lg[t] = a2;
    }
    __syncthreads();
    if (t == 0) {
        float mx = lg[0];
        for (int j = 1; j < NCLASS; j++) mx = fmaxf(mx, lg[j]);
        float se = 0.f;
        for (int j = 0; j < NCLASS; j++) se += expf(lg[j] - mx);
        s_mx = mx; s_ls = logf(se);
    }
    __syncthreads();
    if (t < NCLASS) out[g * NCLASS + t] = lg[t] - s_mx - s_ls;
}

// ---------------- launch ----------------
extern "C" void kernel_launch(void* const* d_in, const int* in_sizes, int n_in,
                              void* d_out, int out_size) {
    const float* x        = (const float*)d_in[0];
    const int*   ei       = (const int*)d_in[1];
    const int*   batch    = (const int*)d_in[2];
    const float* bn_feat  = (const float*)d_in[3];
    const float* w_feat   = (const float*)d_in[4];
    const float* b_feat   = (const float*)d_in[5];
    const float* bns_conv = (const float*)d_in[6];
    const float* gat_w    = (const float*)d_in[7];
    const float* att_s    = (const float*)d_in[8];
    const float* att_d    = (const float*)d_in[9];
    const float* gat_b    = (const float*)d_in[10];
    const float* bns_fc   = (const float*)d_in[11];
    const float* fc_w     = (const float*)d_in[12];
    const float* fc_b     = (const float*)d_in[13];
    const float* bn_hid   = (const float*)d_in[14];
    const float* w_cls    = (const float*)d_in[15];
    const float* b_cls    = (const float*)d_in[16];
    float* out = (float*)d_out;

    float *p_h = nullptr, *p_h2 = nullptr, *p_pool = nullptr;
    int* p_deg = nullptr;
    __nv_bfloat16 *p_hiA = nullptr, *p_loA = nullptr, *p_hiB = nullptr, *p_loB = nullptr;
    cudaGetSymbolAddress((void**)&p_h,    g_h);
    cudaGetSymbolAddress((void**)&p_h2,   g_h2);
    cudaGetSymbolAddress((void**)&p_pool, g_pool);
    cudaGetSymbolAddress((void**)&p_deg,  g_deg);
    cudaGetSymbolAddress((void**)&p_hiA,  g_hiA);
    cudaGetSymbolAddress((void**)&p_loA,  g_loA);
    cudaGetSymbolAddress((void**)&p_hiB,  g_hiB);
    cudaGetSymbolAddress((void**)&p_loB,  g_loB);

    static cudaStream_t s2 = nullptr;
    static cudaEvent_t e0 = nullptr, e1 = nullptr;
    if (!s2) {
        cudaStreamCreateWithFlags(&s2, cudaStreamNonBlocking);
        cudaEventCreateWithFlags(&e0, cudaEventDisableTiming);
        cudaEventCreateWithFlags(&e1, cudaEventDisableTiming);
        cudaFuncSetAttribute(mma_gemm_kernel,
                             cudaFuncAttributeMaxDynamicSharedMemorySize, 8 * BUFE * 2);
    }

    const int GEMM_GRID = (N_NODES + 127) / 128;
    const int GEMM_SMEM = 8 * BUFE * 2;   // 81920 bytes

    // fork: CSR build on s2, feature path on legacy
    cudaEventRecord(e0, 0);
    cudaStreamWaitEvent(s2, e0, 0);

    convx_kernel<<<(N_NODES * HIDDIM / 4 + 255) / 256, 256>>>(x);           // 1
    prep_kernel <<<65, 256>>>(bn_feat, w_feat, b_feat);                     // 2
    cudaMemsetAsync(p_deg, 0, N_NODES * sizeof(int), s2);
    count_kernel<<<(N_EDGES + 255) / 256, 256, 0, s2>>>(ei);                // 3
    mma_gemm_kernel<<<GEMM_GRID, 256, GEMM_SMEM>>>(p_hiA, p_loA,            // 4 <- profiled
                                                   (float*)nullptr, p_hiB, p_loB,
                                                   (const float*)nullptr,
                                                   (const float*)nullptr, 1);
    scanA_kernel<<<NSCH, SCHUNK, 0, s2>>>();                                // 5
    scanB_kernel<<<1, 512, 0, s2>>>();                                      // 6
    scanC_kernel<<<(N_NODES + 255) / 256, 256, 0, s2>>>();                  // 7
    fill_kernel <<<(N_TOT + 255) / 256, 256, 0, s2>>>(ei);                  // 8
    cudaMemsetAsync(p_pool, 0, NGROUP * HIDDIM * sizeof(float), s2);
    cudaEventRecord(e1, s2);

    // conv 0 GEMM can start before CSR finishes; gather needs the join
    prep_kernel<<<65, 256>>>(bns_conv, gat_w, (const float*)nullptr);
    mma_gemm_kernel<<<GEMM_GRID, 256, GEMM_SMEM>>>(p_hiB, p_loB, p_h2,
                                                   (__nv_bfloat16*)nullptr, (__nv_bfloat16*)nullptr,
                                                   att_s, att_d, 0);
    cudaStreamWaitEvent(0, e1, 0);   // join: CSR + pool-memset ready

    __nv_bfloat16* inhi[3] = {p_hiB, p_hiA, p_hiB};
    __nv_bfloat16* inlo[3] = {p_loB, p_loA, p_loB};
    __nv_bfloat16* othi[3] = {p_hiA, p_hiB, (__nv_bfloat16*)nullptr};
    __nv_bfloat16* otlo[3] = {p_loA, p_loB, (__nv_bfloat16*)nullptr};
    for (int i = 0; i < 3; i++) {
        if (i > 0) {
            prep_kernel<<<65, 256>>>(bns_conv + i * 512, gat_w + i * 16384, (const float*)nullptr);
            mma_gemm_kernel<<<GEMM_GRID, 256, GEMM_SMEM>>>(inhi[i], inlo[i], p_h2,
                                                           (__nv_bfloat16*)nullptr, (__nv_bfloat16*)nullptr,
                                                           att_s + i * 128, att_d + i * 128, 0);
        }
        gather_kernel<<<N_NODES / 8, 256>>>(gat_b + i * 128,
                                            (i == 2) ? p_h : (float*)nullptr,
                                            othi[i], otlo[i]);
    }

    pool_kernel <<<NSCH, 128>>>(batch);
    fccls_kernel<<<NGROUP, 128>>>(bns_fc, fc_w, fc_b, bn_hid, w_cls, b_cls, out);
}